// round 10
// baseline (speedup 1.0000x reference)
#include <cuda_runtime.h>
#include <cstdint>

// Problem constants
#define BATCH   1024
#define IN_H    128
#define IN_W    128
#define WPAD    132
#define NKW     25
#define NK      625
#define KHW     100

// Tiling
#define IGROUPS 5            // blockIdx.y
#define KL      125          // outputs per block
#define XROWS   30           // staged padded rows per group
#define XSQ     548          // words per staged row: 132 padded cols * 4 imgs + pad
                             //   5*XSQ mod 32 = 20 -> LDS.128 phases conflict-free
#define BUFQ    (XROWS*XSQ)  // 16440 words per buffer (4 images)
#define HB      4            // images per group (packed in float4)
#define DEPTH   3            // ring buffers, fills 2 ahead
#define BSPLIT  29           // 29*5 = 145 blocks, 1 per SM
#define NT      256
#define SMEM_BYTES (DEPTH*BUFQ*4)   // 197,280 B

// Extracted weights: g_w[k*100 + dy*10 + dx]
__device__ float g_w[NK * KHW];

__global__ void extract_kernel(const float* __restrict__ W)
{
    int idx = blockIdx.x * blockDim.x + threadIdx.x;
    if (idx >= NK * KHW) return;
    int k  = idx / KHW;
    int d  = idx - k * KHW;
    int dy = d / 10;
    int dx = d - dy * 10;
    int ki = k / NKW;
    int kj = k - ki * NKW;
    int r  = (ki * 5 + dy) * WPAD + (kj * 5 + dx);
    g_w[idx] = W[(size_t)r * NK + k];
}

__device__ __forceinline__ void cp4(unsigned int dst_smem, const float* src, int src_sz)
{
    asm volatile("cp.async.ca.shared.global [%0], [%1], 4, %2;\n"
                 :: "r"(dst_smem), "l"(src), "r"(src_sz));
}

// ---------------------------------------------------------------------------
// Image-packed layout: word(rr, cc, img) = rr*XSQ + cc*4 + img, cc = padded
// col 0..131 (real col c at cc=c+2). One LDS.128 yields the same pixel of 4
// images -> 4 independent FMA chains per weight, 4x fewer LDS instructions.
// Warps 0-3 compute (one per SMSP); all 8 warps issue the transposed
// cp.async fill (lane l: img=l>>3, col=c0+(l&7) -> conflict-free STS banks,
// 4x32B coalesced LDG sectors). 3-buffer ring, fills issued 2 groups ahead.
// ---------------------------------------------------------------------------
__global__ __launch_bounds__(NT, 1)
void lc2d_kernel(const float* __restrict__ x,
                 const float* __restrict__ bias,
                 float* __restrict__ out)
{
    extern __shared__ float xs[];
    const unsigned int xs_base = (unsigned int)__cvta_generic_to_shared(xs);

    const int bx  = blockIdx.x;   // 0..28
    const int ig  = blockIdx.y;   // 0..4
    const int tid = threadIdx.x;  // 0..255
    const int wid  = tid >> 5;
    const int lane = tid & 31;

    // zero halo pixel-quads once: padded cols 0,1,130,131 of every row/buffer
    for (int idx = tid; idx < DEPTH * XROWS * 4; idx += NT) {
        int b  = idx >> 2;               // buffer-row index
        int hc = idx & 3;                // which halo col {0,1,130,131}
        int cc = (hc < 2) ? hc : 128 + hc;
        float4* p = reinterpret_cast<float4*>(&xs[b * XSQ + cc * 4]);
        *p = make_float4(0.f, 0.f, 0.f, 0.f);
    }

    const int  kl = (tid < KL) ? tid : KL - 1;
    const bool tv = (tid < KL) && (wid < 4);
    const int  il = kl / 25;
    const int  jj = kl - il * 25;

    // ---- 100 weights into registers (compute warps only use them) ----
    float4 w4[25];
    {
        const float4* wg = reinterpret_cast<const float4*>(g_w) + (ig * KL + kl) * 25;
        #pragma unroll
        for (int j = 0; j < 25; ++j) w4[j] = __ldg(&wg[j]);
    }
    const float bv = __ldg(&bias[ig * KL + kl]);

    const int r0       = ig * 25 - 2;
    const int nb_total = (BATCH - 1 - bx) / BSPLIT + 1;   // 35 or 36
    const int NG       = (nb_total + HB - 1) / HB;        // 9

    // fill lane roles (constant per thread)
    const int f_img = lane >> 3;          // 0..3
    const int f_c   = lane & 7;           // col within 8-block

    // fill buffer (hg % DEPTH) with group hg (4 images, transposed pack)
    auto fill = [&](int hg) {
        int buf = hg % DEPTH;
        int t   = hg * HB + f_img;        // image slot for this lane
        bool tval = t < nb_total;
        const float* img_base = x + (size_t)(bx + t * BSPLIT) * (IN_H * IN_W) + f_c;
        unsigned int dst_base = xs_base +
            (unsigned int)(buf * BUFQ + 8 + 4 * f_c + f_img) * 4u; // cc = c+2
        // tasks tau = wid*60 + it : r = tau/16, c0 = (tau%16)*8
        #pragma unroll
        for (int it = 0; it < 60; ++it) {
            int tau = wid * 60 + it;
            int r   = tau >> 4;
            int c0  = (tau & 15) << 3;
            int rr  = r0 + r;
            bool v  = tval & (rr >= 0) & (rr < IN_H);
            const float* src = v ? (img_base + rr * IN_W + c0) : x;
            unsigned int dst = dst_base + (unsigned int)(r * XSQ + c0 * 4) * 4u;
            cp4(dst, src, v ? 4 : 0);
        }
        asm volatile("cp.async.commit_group;\n");
    };

    fill(0);
    fill(1);

    const int xoff = il * 5 * XSQ + jj * 20;   // quad-aligned word offset

    for (int g = 0; g < NG; ++g) {
        if (g + 1 < NG) asm volatile("cp.async.wait_group 1;\n");
        else            asm volatile("cp.async.wait_group 0;\n");
        __syncthreads();

        // issue next fill first (targets buffer consumed at iteration g-1)
        if (g + 2 < NG) fill(g + 2);

        if (wid < 4) {
            const float* xp = xs + (g % DEPTH) * BUFQ + xoff;
            float4 acc0 = make_float4(0.f, 0.f, 0.f, 0.f);
            float4 acc1 = make_float4(0.f, 0.f, 0.f, 0.f);
            const float* wf = reinterpret_cast<const float*>(w4);
            #pragma unroll
            for (int dy = 0; dy < 10; ++dy) {
                const float* row = xp + dy * XSQ;
                const float* wr  = wf + dy * 10;
                #pragma unroll
                for (int dx = 0; dx < 10; dx += 2) {
                    float4 v0 = *reinterpret_cast<const float4*>(row + dx * 4);
                    float4 v1 = *reinterpret_cast<const float4*>(row + dx * 4 + 4);
                    float w0 = wr[dx], w1 = wr[dx + 1];
                    acc0.x = fmaf(v0.x, w0, acc0.x);
                    acc0.y = fmaf(v0.y, w0, acc0.y);
                    acc0.z = fmaf(v0.z, w0, acc0.z);
                    acc0.w = fmaf(v0.w, w0, acc0.w);
                    acc1.x = fmaf(v1.x, w1, acc1.x);
                    acc1.y = fmaf(v1.y, w1, acc1.y);
                    acc1.z = fmaf(v1.z, w1, acc1.z);
                    acc1.w = fmaf(v1.w, w1, acc1.w);
                }
            }
            if (tv) {
                float r4[4] = { acc0.x + acc1.x + bv, acc0.y + acc1.y + bv,
                                acc0.z + acc1.z + bv, acc0.w + acc1.w + bv };
                int tA = g * HB;
                int ob = ig * KL + kl;
                #pragma unroll
                for (int i = 0; i < 4; ++i)
                    if (tA + i < nb_total)
                        out[(size_t)(bx + (tA + i) * BSPLIT) * NK + ob] = r4[i];
            }
        }
        __syncthreads();
    }
}

// ---------------------------------------------------------------------------
extern "C" void kernel_launch(void* const* d_in, const int* in_sizes, int n_in,
                              void* d_out, int out_size)
{
    const float* x    = (const float*)d_in[0];   // [1024,128,128]
    const float* W    = (const float*)d_in[1];   // [17424,625]
    const float* bias = (const float*)d_in[2];   // [25,25]
    float* out = (float*)d_out;                  // [1024,25,25]

    cudaFuncSetAttribute(lc2d_kernel,
                         cudaFuncAttributeMaxDynamicSharedMemorySize, SMEM_BYTES);

    extract_kernel<<<(NK * KHW + 255) / 256, 256>>>(W);

    dim3 grid(BSPLIT, IGROUPS);
    lc2d_kernel<<<grid, NT, SMEM_BYTES>>>(x, bias, out);
}

// round 11
// speedup vs baseline: 1.0073x; 1.0073x over previous
#include <cuda_runtime.h>
#include <cstdint>

// Problem constants
#define BATCH   1024
#define IN_H    128
#define IN_W    128
#define WPAD    132
#define NKW     25
#define NK      625
#define KHW     100

// Tiling
#define IGROUPS 5            // blockIdx.y
#define KL      125          // outputs per block
#define XROWS   30           // staged padded rows per group
#define XSQ     548          // words per staged row: 132 padded cols * 4 imgs + pad
                             //   5*XSQ mod 32 = 20 -> LDS.128 phases conflict-free
#define BUFQ    (XROWS*XSQ)  // 16440 words per buffer (4 images)
#define HB      4            // images per group (packed in float4)
#define DEPTH   3            // ring buffers, fills 2 ahead
#define BSPLIT  29           // 29*5 = 145 blocks, 1 per SM
#define NT      256
#define SMEM_BYTES (DEPTH*BUFQ*4)   // 197,280 B

// Extracted weights: g_w[k*100 + dy*10 + dx]
__device__ float g_w[NK * KHW];

__global__ void extract_kernel(const float* __restrict__ W)
{
    int idx = blockIdx.x * blockDim.x + threadIdx.x;
    if (idx >= NK * KHW) return;
    int k  = idx / KHW;
    int d  = idx - k * KHW;
    int dy = d / 10;
    int dx = d - dy * 10;
    int ki = k / NKW;
    int kj = k - ki * NKW;
    int r  = (ki * 5 + dy) * WPAD + (kj * 5 + dx);
    g_w[idx] = W[(size_t)r * NK + k];
}

__device__ __forceinline__ void cp4(unsigned int dst_smem, const float* src, int src_sz)
{
    asm volatile("cp.async.ca.shared.global [%0], [%1], 4, %2;\n"
                 :: "r"(dst_smem), "l"(src), "r"(src_sz));
}

// ---------------------------------------------------------------------------
// Image-packed layout: word(rr, cc, img) = rr*XSQ + cc*4 + img, cc = padded
// col 0..131 (real col c at cc=c+2). One LDS.128 yields the same pixel of 4
// images -> 4 independent FMA chains per weight, 4x fewer LDS instructions.
// Warps 0-3 compute (one per SMSP); all 8 warps issue the transposed
// cp.async fill (lane l: img=l>>3, col=c0+(l&7) -> conflict-free STS banks,
// 4x32B coalesced LDG sectors). 3-buffer ring, fills issued 2 groups ahead.
// ---------------------------------------------------------------------------
__global__ __launch_bounds__(NT, 1)
void lc2d_kernel(const float* __restrict__ x,
                 const float* __restrict__ bias,
                 float* __restrict__ out)
{
    extern __shared__ float xs[];
    const unsigned int xs_base = (unsigned int)__cvta_generic_to_shared(xs);

    const int bx  = blockIdx.x;   // 0..28
    const int ig  = blockIdx.y;   // 0..4
    const int tid = threadIdx.x;  // 0..255
    const int wid  = tid >> 5;
    const int lane = tid & 31;

    // zero halo pixel-quads once: padded cols 0,1,130,131 of every row/buffer
    for (int idx = tid; idx < DEPTH * XROWS * 4; idx += NT) {
        int b  = idx >> 2;               // buffer-row index
        int hc = idx & 3;                // which halo col {0,1,130,131}
        int cc = (hc < 2) ? hc : 128 + hc;
        float4* p = reinterpret_cast<float4*>(&xs[b * XSQ + cc * 4]);
        *p = make_float4(0.f, 0.f, 0.f, 0.f);
    }

    const int  kl = (tid < KL) ? tid : KL - 1;
    const bool tv = (tid < KL) && (wid < 4);
    const int  il = kl / 25;
    const int  jj = kl - il * 25;

    // ---- 100 weights into registers (compute warps only use them) ----
    float4 w4[25];
    {
        const float4* wg = reinterpret_cast<const float4*>(g_w) + (ig * KL + kl) * 25;
        #pragma unroll
        for (int j = 0; j < 25; ++j) w4[j] = __ldg(&wg[j]);
    }
    const float bv = __ldg(&bias[ig * KL + kl]);

    const int r0       = ig * 25 - 2;
    const int nb_total = (BATCH - 1 - bx) / BSPLIT + 1;   // 35 or 36
    const int NG       = (nb_total + HB - 1) / HB;        // 9

    // fill lane roles (constant per thread)
    const int f_img = lane >> 3;          // 0..3
    const int f_c   = lane & 7;           // col within 8-block

    // fill buffer (hg % DEPTH) with group hg (4 images, transposed pack)
    auto fill = [&](int hg) {
        int buf = hg % DEPTH;
        int t   = hg * HB + f_img;        // image slot for this lane
        bool tval = t < nb_total;
        const float* img_base = x + (size_t)(bx + t * BSPLIT) * (IN_H * IN_W) + f_c;
        unsigned int dst_base = xs_base +
            (unsigned int)(buf * BUFQ + 8 + 4 * f_c + f_img) * 4u; // cc = c+2
        // tasks tau = wid*60 + it : r = tau/16, c0 = (tau%16)*8
        #pragma unroll
        for (int it = 0; it < 60; ++it) {
            int tau = wid * 60 + it;
            int r   = tau >> 4;
            int c0  = (tau & 15) << 3;
            int rr  = r0 + r;
            bool v  = tval & (rr >= 0) & (rr < IN_H);
            const float* src = v ? (img_base + rr * IN_W + c0) : x;
            unsigned int dst = dst_base + (unsigned int)(r * XSQ + c0 * 4) * 4u;
            cp4(dst, src, v ? 4 : 0);
        }
        asm volatile("cp.async.commit_group;\n");
    };

    fill(0);
    fill(1);

    const int xoff = il * 5 * XSQ + jj * 20;   // quad-aligned word offset

    for (int g = 0; g < NG; ++g) {
        if (g + 1 < NG) asm volatile("cp.async.wait_group 1;\n");
        else            asm volatile("cp.async.wait_group 0;\n");
        __syncthreads();

        // issue next fill first (targets buffer consumed at iteration g-1)
        if (g + 2 < NG) fill(g + 2);

        if (wid < 4) {
            const float* xp = xs + (g % DEPTH) * BUFQ + xoff;
            float4 acc0 = make_float4(0.f, 0.f, 0.f, 0.f);
            float4 acc1 = make_float4(0.f, 0.f, 0.f, 0.f);
            const float* wf = reinterpret_cast<const float*>(w4);
            #pragma unroll
            for (int dy = 0; dy < 10; ++dy) {
                const float* row = xp + dy * XSQ;
                const float* wr  = wf + dy * 10;
                #pragma unroll
                for (int dx = 0; dx < 10; dx += 2) {
                    float4 v0 = *reinterpret_cast<const float4*>(row + dx * 4);
                    float4 v1 = *reinterpret_cast<const float4*>(row + dx * 4 + 4);
                    float w0 = wr[dx], w1 = wr[dx + 1];
                    acc0.x = fmaf(v0.x, w0, acc0.x);
                    acc0.y = fmaf(v0.y, w0, acc0.y);
                    acc0.z = fmaf(v0.z, w0, acc0.z);
                    acc0.w = fmaf(v0.w, w0, acc0.w);
                    acc1.x = fmaf(v1.x, w1, acc1.x);
                    acc1.y = fmaf(v1.y, w1, acc1.y);
                    acc1.z = fmaf(v1.z, w1, acc1.z);
                    acc1.w = fmaf(v1.w, w1, acc1.w);
                }
            }
            if (tv) {
                float r4[4] = { acc0.x + acc1.x + bv, acc0.y + acc1.y + bv,
                                acc0.z + acc1.z + bv, acc0.w + acc1.w + bv };
                int tA = g * HB;
                int ob = ig * KL + kl;
                #pragma unroll
                for (int i = 0; i < 4; ++i)
                    if (tA + i < nb_total)
                        out[(size_t)(bx + (tA + i) * BSPLIT) * NK + ob] = r4[i];
            }
        }
        __syncthreads();
    }
}

// ---------------------------------------------------------------------------
extern "C" void kernel_launch(void* const* d_in, const int* in_sizes, int n_in,
                              void* d_out, int out_size)
{
    const float* x    = (const float*)d_in[0];   // [1024,128,128]
    const float* W    = (const float*)d_in[1];   // [17424,625]
    const float* bias = (const float*)d_in[2];   // [25,25]
    float* out = (float*)d_out;                  // [1024,25,25]

    cudaFuncSetAttribute(lc2d_kernel,
                         cudaFuncAttributeMaxDynamicSharedMemorySize, SMEM_BYTES);

    extract_kernel<<<(NK * KHW + 255) / 256, 256>>>(W);

    dim3 grid(BSPLIT, IGROUPS);
    lc2d_kernel<<<grid, NT, SMEM_BYTES>>>(x, bias, out);
}